// round 12
// baseline (speedup 1.0000x reference)
#include <cuda_runtime.h>
#include <cuda_fp16.h>
#include <cstdint>
#include <cfloat>

#define NB 64
#define NC 8
#define NH 256
#define NW 256
#define HW (NH*NW)

// Scratch (__device__ globals per allocation-free rule)
// q/k layout (validated R9-11): per 256-half row r, element j at
//   ((j>>4 ^ (r&3)) << 4) + kperm16(j & 15).
// vth layout (NEW, paired): per 256-half row r, element j at
//   (( (j>>5) ^ (r&7) )*32) + t4j*8 + ((j>>4)&1)*4 + halfj*2 + (j&1)
//   where pk=(j&15)>>1, t4j=pk&3, halfj=pk>>2.  One LDS.128 per kb-pair.
__device__ __half g_qh[NB*HW], g_ql[NB*HW];    // q hi/lo fp16 (3-term split)
__device__ __half g_kh[NB*HW], g_kl[NB*HW];    // k hi/lo fp16
__device__ __half g_vth[(size_t)NB*NC*HW];     // fp16 v^T [b][c][w][j], paired layout

// ---------------------------------------------------------------------------
// helpers
// ---------------------------------------------------------------------------
__device__ __forceinline__ uint32_t smem_u32(const void* p) {
    uint32_t a;
    asm("{ .reg .u64 t; cvta.to.shared.u64 t, %1; cvt.u32.u64 %0, t; }" : "=r"(a) : "l"(p));
    return a;
}
__device__ __forceinline__ uint2 lds64(uint32_t a) {
    uint2 v;
    asm volatile("ld.shared.v2.u32 {%0,%1}, [%2];" : "=r"(v.x), "=r"(v.y) : "r"(a));
    return v;
}
__device__ __forceinline__ uint4 lds128u(uint32_t a) {
    uint4 v;
    asm volatile("ld.shared.v4.u32 {%0,%1,%2,%3}, [%4];"
                 : "=r"(v.x), "=r"(v.y), "=r"(v.z), "=r"(v.w) : "r"(a));
    return v;
}
// exp(x) for x <= 0, FMA-pipe only: 2^(x*log2e), deg-6 poly
__device__ __forceinline__ float fast_exp(float x) {
    float t = fmaxf(x * 1.4426950408889634f, -126.0f);
    float n = rintf(t);
    float f = t - n;
    float p = fmaf(f, 0.00015403530393381609f, 0.0013333558146428443f);
    p = fmaf(f, p, 0.009618129107628477f);
    p = fmaf(f, p, 0.0555041086648216f);
    p = fmaf(f, p, 0.2402265069591007f);
    p = fmaf(f, p, 0.6931471805599453f);
    p = fmaf(f, p, 1.0f);
    return __int_as_float(__float_as_int(p) + (((int)n) << 23));
}
#define MBAR_INIT(a, n) asm volatile("mbarrier.init.shared.b64 [%0], %1;" :: "r"(a), "r"(n) : "memory")
#define MBAR_EXPECT(a, tx) asm volatile("mbarrier.arrive.expect_tx.shared.b64 _, [%0], %1;" :: "r"(a), "r"(tx) : "memory")
#define MBAR_WAIT(a, ph) do {                                                        \
    uint32_t _m = (a), _p = (ph), _d;                                                \
    asm volatile("{ .reg .pred p; mbarrier.try_wait.parity.acquire.cta.shared::cta.b64 p, [%1], %2; selp.b32 %0,1,0,p; }" \
                 : "=r"(_d) : "r"(_m), "r"(_p) : "memory");                          \
    if (!_d) {                                                                       \
      asm volatile("{ .reg .pred P1; WL%=: mbarrier.try_wait.parity.acquire.cta.shared::cta.b64 P1, [%0], %1, 0x989680; @P1 bra.uni WD%=; bra.uni WL%=; WD%=: }" \
                   :: "r"(_m), "r"(_p) : "memory");                                  \
    } } while (0)
#define BULK_G2S(sdst, gsrc, bytes, mbar)                                            \
    asm volatile("cp.async.bulk.shared::cta.global.mbarrier::complete_tx::bytes "    \
                 "[%0], [%1], %2, [%3];"                                             \
                 :: "r"(sdst), "l"(gsrc), "r"(bytes), "r"(mbar) : "memory")
#define MMA_F16(d, a0, a1, a2, a3, b0, b1)                                        \
    asm volatile("mma.sync.aligned.m16n8k16.row.col.f32.f16.f16.f32 "             \
                 "{%0,%1,%2,%3},{%4,%5,%6,%7},{%8,%9},{%0,%1,%2,%3};"             \
                 : "+f"(d[0]), "+f"(d[1]), "+f"(d[2]), "+f"(d[3])                  \
                 : "r"(a0), "r"(a1), "r"(a2), "r"(a3), "r"(b0), "r"(b1))

__device__ __forceinline__ int kperm16(int kb) {   // kb = k & 15
    int pk = kb >> 1;
    return ((((pk & 3) << 1) | (pk >> 2)) << 1) | (kb & 1);
}
// paired layout offset (halfs) for even j, row r:
__device__ __forceinline__ int pairoff(int j, int r) {
    int pk = (j & 15) >> 1;
    return (((j >> 5) ^ (r & 7)) << 5) + (pk & 3) * 8 + ((j >> 4) & 1) * 4
           + (pk >> 2) * 2;
}

// ---------------------------------------------------------------------------
// Kernel A: fused projections. q,k -> fp16 hi/lo (old layout, validated);
// v = w3@x + b3 transposed [b][c][w][j], fp16, NEW paired layout.
// ---------------------------------------------------------------------------
__global__ __launch_bounds__(256)
void proj_kernel(const float* __restrict__ x,
                 const float* __restrict__ w1, const float* __restrict__ b1,
                 const float* __restrict__ w2, const float* __restrict__ b2,
                 const float* __restrict__ w3, const float* __restrict__ b3) {
    __shared__ float xt_s[8][32][33];
    __shared__ float w1s[8], w2s[8], w3s[64], b3s[8], bqk[2];
    const int tid = threadIdx.x;
    if (tid < 8)  { w1s[tid] = w1[tid]; w2s[tid] = w2[tid]; b3s[tid] = b3[tid]; }
    if (tid < 64) w3s[tid] = w3[tid];
    if (tid == 0) { bqk[0] = b1[0]; bqk[1] = b2[0]; }
    __syncthreads();
    const int b = blockIdx.z, j0 = blockIdx.y * 32, w0 = blockIdx.x * 32;
    const int jl = tid >> 3, wq = (tid & 7) << 2;
    const float* xb = x + (size_t)b * NC * HW + (size_t)(j0 + jl) * NW + w0 + wq;

    float4 xv[8];
#pragma unroll
    for (int c = 0; c < 8; c++) xv[c] = *(const float4*)(xb + (size_t)c * HW);

    float4 q = make_float4(bqk[0], bqk[0], bqk[0], bqk[0]);
    float4 k = make_float4(bqk[1], bqk[1], bqk[1], bqk[1]);
#pragma unroll
    for (int c = 0; c < 8; c++) {
        q.x = fmaf(w1s[c], xv[c].x, q.x); q.y = fmaf(w1s[c], xv[c].y, q.y);
        q.z = fmaf(w1s[c], xv[c].z, q.z); q.w = fmaf(w1s[c], xv[c].w, q.w);
        k.x = fmaf(w2s[c], xv[c].x, k.x); k.y = fmaf(w2s[c], xv[c].y, k.y);
        k.z = fmaf(w2s[c], xv[c].z, k.z); k.w = fmaf(w2s[c], xv[c].w, k.w);
    }
    {
        const int row = j0 + jl;
        const size_t rowoff = (size_t)b * HW + (size_t)row * NW;
        const int base = (((w0 + wq) >> 4) ^ (row & 3)) << 4;
        const int kb = wq & 15;
        const int h0 = base + kperm16(kb), h1 = base + kperm16(kb + 2);
        __half qhx = __float2half_rn(q.x), qhy = __float2half_rn(q.y);
        __half qhz = __float2half_rn(q.z), qhw = __float2half_rn(q.w);
        __half khx = __float2half_rn(k.x), khy = __float2half_rn(k.y);
        __half khz = __float2half_rn(k.z), khw = __float2half_rn(k.w);
        *(__half2*)(g_qh + rowoff + h0) = __halves2half2(qhx, qhy);
        *(__half2*)(g_qh + rowoff + h1) = __halves2half2(qhz, qhw);
        *(__half2*)(g_kh + rowoff + h0) = __halves2half2(khx, khy);
        *(__half2*)(g_kh + rowoff + h1) = __halves2half2(khz, khw);
        *(__half2*)(g_ql + rowoff + h0) = __floats2half2_rn(q.x - __half2float(qhx),
                                                            q.y - __half2float(qhy));
        *(__half2*)(g_ql + rowoff + h1) = __floats2half2_rn(q.z - __half2float(qhz),
                                                            q.w - __half2float(qhw));
        *(__half2*)(g_kl + rowoff + h0) = __floats2half2_rn(k.x - __half2float(khx),
                                                            k.y - __half2float(khy));
        *(__half2*)(g_kl + rowoff + h1) = __floats2half2_rn(k.z - __half2float(khz),
                                                            k.w - __half2float(khw));
    }

#pragma unroll
    for (int c = 0; c < 8; c++) {
        float4 v = make_float4(b3s[c], b3s[c], b3s[c], b3s[c]);
#pragma unroll
        for (int cp = 0; cp < 8; cp++) {
            float w = w3s[c * 8 + cp];
            v.x = fmaf(w, xv[cp].x, v.x); v.y = fmaf(w, xv[cp].y, v.y);
            v.z = fmaf(w, xv[cp].z, v.z); v.w = fmaf(w, xv[cp].w, v.w);
        }
        xt_s[c][jl][wq + 0] = v.x; xt_s[c][jl][wq + 1] = v.y;
        xt_s[c][jl][wq + 2] = v.z; xt_s[c][jl][wq + 3] = v.w;
    }
    __syncthreads();
    // transposed fp16 write in NEW paired layout (row = w, k-index = j)
    const int jp = (tid & 15) << 1, wl = tid >> 4;
#pragma unroll
    for (int c = 0; c < 8; c++)
#pragma unroll
        for (int ws = 0; ws < 32; ws += 16) {
            int wg = ws + wl;
            int idx = pairoff(j0 + jp, wg);
            *(__half2*)(g_vth + (((size_t)(b * 8 + c)) * NW + w0 + wg) * NH + idx) =
                __floats2half2_rn(xt_s[c][jp][wg], xt_s[c][jp + 1][wg]);
        }
}

// ---------------------------------------------------------------------------
// Kernel B: MERGED attention. Phase 1 = scores+softmax (validated R11 path,
// fp16 3-term split, q resident / k ring). Phase 2 = out = attn @ vth for all
// 8 channels, attn in smem (paired layout), vth bulk-filled per channel into
// the dead q region. CTA = (mt, b), 512 thr = 16 warps (4m x 4n).
// ---------------------------------------------------------------------------
#define SF_MB_F0 0
#define SF_MB_F1 8
#define SF_MB_A  16
#define SF_MB_V  24
#define SF_QH 1024
#define SF_QL (SF_QH + 65536)
#define SF_ATTN (SF_QL + 65536)       // k-ring during phase1, attn in phase2
#define SF_RED (SF_ATTN + 65536)
#define SMEM_FUSED (SF_RED + 2048)    // 199680
#define SF_V SF_QH                    // phase-2 vth slot (128KB, former q)

__global__ __launch_bounds__(512, 1)
void attention_kernel(float* __restrict__ out) {
    extern __shared__ char smem[];
    const uint32_t sb = smem_u32(smem);
    float* red = (float*)(smem + SF_RED);
    const int tid = threadIdx.x;
    const int lane = tid & 31, warp = tid >> 5;
    const int warpM = warp & 3, warpN = warp >> 2;
    const int g = lane >> 2, t4 = lane & 3;
    const uint32_t gx = (uint32_t)(g & 3);

    const int mt = blockIdx.x;
    const int b  = blockIdx.y;
    const int i0 = mt * 128;
    const __half* Aqh = g_qh + (size_t)b * HW + (size_t)i0 * NW;
    const __half* Aql = g_ql + (size_t)b * HW + (size_t)i0 * NW;
    const __half* Bkh = g_kh + (size_t)b * HW;
    const __half* Bkl = g_kl + (size_t)b * HW;

    if (tid == 0) {
        MBAR_INIT(sb + SF_MB_F0, 1);
        MBAR_INIT(sb + SF_MB_F1, 1);
        MBAR_INIT(sb + SF_MB_A, 1);
        MBAR_INIT(sb + SF_MB_V, 1);
    }
    __syncthreads();
    if (tid == 0) {
        MBAR_EXPECT(sb + SF_MB_A, 131072u);
        BULK_G2S(sb + SF_QH, Aqh, 65536u, sb + SF_MB_A);
        BULK_G2S(sb + SF_QL, Aql, 65536u, sb + SF_MB_A);
        MBAR_EXPECT(sb + SF_MB_F0, 32768u);
        BULK_G2S(sb + SF_ATTN,          Bkh, 16384u, sb + SF_MB_F0);
        BULK_G2S(sb + SF_ATTN + 16384,  Bkl, 16384u, sb + SF_MB_F0);
        MBAR_EXPECT(sb + SF_MB_F1, 32768u);
        BULK_G2S(sb + SF_ATTN + 32768,  Bkh + 32 * NH, 16384u, sb + SF_MB_F1);
        BULK_G2S(sb + SF_ATTN + 49152,  Bkl + 32 * NH, 16384u, sb + SF_MB_F1);
    }

    float acc[8][2][4];
#pragma unroll
    for (int t = 0; t < 8; t++)
#pragma unroll
        for (int mi = 0; mi < 2; mi++)
#pragma unroll
            for (int r = 0; r < 4; r++) acc[t][mi][r] = 0.f;

    MBAR_WAIT(sb + SF_MB_A, 0);

    const int nrow = warpN * 8 + g;
#pragma unroll
    for (int t = 0; t < 8; t++) {
        MBAR_WAIT(sb + ((t & 1) ? SF_MB_F1 : SF_MB_F0), (t >> 1) & 1);
        const uint32_t kh = sb + SF_ATTN + (t & 1) * 32768;
        const uint32_t kl = kh + 16384;
        for (int kb = 0; kb < 16; kb++) {
            const uint32_t off = ((uint32_t)(kb ^ (int)gx) << 5) + (uint32_t)(t4 * 8);
            uint32_t ah[2][4], al[2][4];
#pragma unroll
            for (int mi = 0; mi < 2; mi++) {
                int r0 = warpM * 32 + mi * 16 + g;
                uint2 h0 = lds64(sb + SF_QH + r0 * 512 + off);
                uint2 h1 = lds64(sb + SF_QH + (r0 + 8) * 512 + off);
                uint2 l0 = lds64(sb + SF_QL + r0 * 512 + off);
                uint2 l1 = lds64(sb + SF_QL + (r0 + 8) * 512 + off);
                ah[mi][0] = h0.x; ah[mi][1] = h1.x; ah[mi][2] = h0.y; ah[mi][3] = h1.y;
                al[mi][0] = l0.x; al[mi][1] = l1.x; al[mi][2] = l0.y; al[mi][3] = l1.y;
            }
            uint2 bh = lds64(kh + nrow * 512 + off);
            uint2 bl = lds64(kl + nrow * 512 + off);
#pragma unroll
            for (int mi = 0; mi < 2; mi++) {
                MMA_F16(acc[t][mi], ah[mi][0], ah[mi][1], ah[mi][2], ah[mi][3],
                        bh.x, bh.y);
                MMA_F16(acc[t][mi], ah[mi][0], ah[mi][1], ah[mi][2], ah[mi][3],
                        bl.x, bl.y);
                MMA_F16(acc[t][mi], al[mi][0], al[mi][1], al[mi][2], al[mi][3],
                        bh.x, bh.y);
            }
        }
        __syncthreads();
        if (tid == 0 && t < 6) {
            uint32_t mb = sb + ((t & 1) ? SF_MB_F1 : SF_MB_F0);
            MBAR_EXPECT(mb, 32768u);
            uint32_t dst = sb + SF_ATTN + (t & 1) * 32768;
            BULK_G2S(dst,         Bkh + (size_t)(t + 2) * 32 * NH, 16384u, mb);
            BULK_G2S(dst + 16384, Bkl + (size_t)(t + 2) * 32 * NH, 16384u, mb);
        }
    }
    // q region now dead -> start filling vth for c=0 (overlaps softmax)
    if (tid == 0) {
        MBAR_EXPECT(sb + SF_MB_V, 131072u);
        BULK_G2S(sb + SF_V, g_vth + ((size_t)(b * 8)) * HW, 131072u, sb + SF_MB_V);
    }

    // ---- softmax (in regs, cross-warp reduce via red[]) ----
    float rowv[4];
#pragma unroll
    for (int mi = 0; mi < 2; mi++)
#pragma unroll
        for (int h = 0; h < 2; h++) {
            float m = -FLT_MAX;
#pragma unroll
            for (int t = 0; t < 8; t++)
                m = fmaxf(m, fmaxf(acc[t][mi][h * 2], acc[t][mi][h * 2 + 1]));
            m = fmaxf(m, __shfl_xor_sync(0xffffffffu, m, 1));
            m = fmaxf(m, __shfl_xor_sync(0xffffffffu, m, 2));
            rowv[mi * 2 + h] = m;
        }
    if (t4 == 0) {
#pragma unroll
        for (int mi = 0; mi < 2; mi++)
#pragma unroll
            for (int h = 0; h < 2; h++)
                red[warpN * 128 + warpM * 32 + mi * 16 + h * 8 + g] = rowv[mi * 2 + h];
    }
    __syncthreads();
    float rowmax[4];
#pragma unroll
    for (int mi = 0; mi < 2; mi++)
#pragma unroll
        for (int h = 0; h < 2; h++) {
            int rl = warpM * 32 + mi * 16 + h * 8 + g;
            rowmax[mi * 2 + h] = fmaxf(fmaxf(red[rl], red[128 + rl]),
                                       fmaxf(red[256 + rl], red[384 + rl]));
        }
    __syncthreads();
#pragma unroll
    for (int mi = 0; mi < 2; mi++)
#pragma unroll
        for (int h = 0; h < 2; h++) {
            float m = rowmax[mi * 2 + h], s = 0.f;
#pragma unroll
            for (int t = 0; t < 8; t++) {
                float e0 = fast_exp(acc[t][mi][h * 2] - m);
                float e1 = fast_exp(acc[t][mi][h * 2 + 1] - m);
                acc[t][mi][h * 2] = e0; acc[t][mi][h * 2 + 1] = e1;
                s += e0 + e1;
            }
            s += __shfl_xor_sync(0xffffffffu, s, 1);
            s += __shfl_xor_sync(0xffffffffu, s, 2);
            rowv[mi * 2 + h] = s;
        }
    if (t4 == 0) {
#pragma unroll
        for (int mi = 0; mi < 2; mi++)
#pragma unroll
            for (int h = 0; h < 2; h++)
                red[warpN * 128 + warpM * 32 + mi * 16 + h * 8 + g] = rowv[mi * 2 + h];
    }
    __syncthreads();   // also: all k-ring reads done; SF_ATTN region reusable
    // ---- store attn (fp16) to smem in paired layout ----
#pragma unroll
    for (int mi = 0; mi < 2; mi++)
#pragma unroll
        for (int h = 0; h < 2; h++) {
            int rl = warpM * 32 + mi * 16 + h * 8 + g;
            float inv = 1.0f / (red[rl] + red[128 + rl] + red[256 + rl] + red[384 + rl]);
#pragma unroll
            for (int t = 0; t < 8; t++) {
                int j = t * 32 + warpN * 8 + t4 * 2;
                uint32_t addr = sb + SF_ATTN + rl * 512 + pairoff(j, rl) * 2;
                __half2 hv = __floats2half2_rn(acc[t][mi][h * 2] * inv,
                                               acc[t][mi][h * 2 + 1] * inv);
                asm volatile("st.shared.b32 [%0], %1;" :: "r"(addr),
                             "r"(*(uint32_t*)&hv) : "memory");
            }
        }
    __syncthreads();

    // ================= Phase 2: out[c] = attn @ vth[b][c] =================
    for (int c = 0; c < 8; c++) {
        MBAR_WAIT(sb + SF_MB_V, c & 1);

        float oacc[2][8][4];
#pragma unroll
        for (int mi = 0; mi < 2; mi++)
#pragma unroll
            for (int ni = 0; ni < 8; ni++)
#pragma unroll
                for (int r = 0; r < 4; r++) oacc[mi][ni][r] = 0.f;

        for (int p = 0; p < 8; p++) {           // kb-pairs
            uint4 av[2][2];
#pragma unroll
            for (int mi = 0; mi < 2; mi++) {
                int r0 = warpM * 32 + mi * 16 + g;
                uint32_t xo = ((uint32_t)(p ^ (r0 & 7)) << 6) + (uint32_t)(t4 * 16);
                av[mi][0] = lds128u(sb + SF_ATTN + r0 * 512 + xo);
                av[mi][1] = lds128u(sb + SF_ATTN + (r0 + 8) * 512 + xo);
            }
#pragma unroll
            for (int ni = 0; ni < 8; ni++) {
                int n = warpN * 64 + ni * 8 + g;
                uint32_t xo = ((uint32_t)(p ^ (n & 7)) << 6) + (uint32_t)(t4 * 16);
                uint4 bv = lds128u(sb + SF_V + n * 512 + xo);
#pragma unroll
                for (int mi = 0; mi < 2; mi++) {
                    MMA_F16(oacc[mi][ni], av[mi][0].x, av[mi][1].x,
                            av[mi][0].y, av[mi][1].y, bv.x, bv.y);
                    MMA_F16(oacc[mi][ni], av[mi][0].z, av[mi][1].z,
                            av[mi][0].w, av[mi][1].w, bv.z, bv.w);
                }
            }
        }

        __syncthreads();                        // all vth[c] reads done
        if (tid == 0 && c < 7) {
            MBAR_EXPECT(sb + SF_MB_V, 131072u);
            BULK_G2S(sb + SF_V, g_vth + ((size_t)(b * 8 + c + 1)) * HW,
                     131072u, sb + SF_MB_V);
        }

        // epilogue (overlaps next vth fill)
        float* ob = out + ((size_t)(b * 8 + c)) * HW;
#pragma unroll
        for (int mi = 0; mi < 2; mi++) {
            int row = i0 + warpM * 32 + mi * 16 + g;
#pragma unroll
            for (int ni = 0; ni < 8; ni++) {
                int col = warpN * 64 + ni * 8 + t4 * 2;
                *(float2*)(ob + (size_t)row * NW + col) =
                    make_float2(oacc[mi][ni][0], oacc[mi][ni][1]);
                *(float2*)(ob + (size_t)(row + 8) * NW + col) =
                    make_float2(oacc[mi][ni][2], oacc[mi][ni][3]);
            }
        }
    }
}

// ---------------------------------------------------------------------------
extern "C" void kernel_launch(void* const* d_in, const int* in_sizes, int n_in,
                              void* d_out, int out_size) {
    const float* x  = (const float*)d_in[0];
    const float* w1 = (const float*)d_in[1];
    const float* b1 = (const float*)d_in[2];
    const float* w2 = (const float*)d_in[3];
    const float* b2 = (const float*)d_in[4];
    const float* w3 = (const float*)d_in[5];
    const float* b3 = (const float*)d_in[6];
    float* out = (float*)d_out;

    static bool configured = false;
    if (!configured) {
        cudaFuncSetAttribute(attention_kernel,
                             cudaFuncAttributeMaxDynamicSharedMemorySize, SMEM_FUSED);
        configured = true;
    }

    dim3 ga(8, 8, NB);
    proj_kernel<<<ga, 256>>>(x, w1, b1, w2, b2, w3, b3);
    dim3 gs(2, NB);
    attention_kernel<<<gs, 512, SMEM_FUSED>>>(out);
}

// round 13
// speedup vs baseline: 1.0348x; 1.0348x over previous
#include <cuda_runtime.h>
#include <cuda_fp16.h>
#include <cstdint>
#include <cfloat>

#define NB 64
#define NC 8
#define NH 256
#define NW 256
#define HW (NH*NW)

// Scratch (__device__ globals per allocation-free rule)
// q/k layout (validated R9-12): per 256-half row r, element j at
//   ((j>>4 ^ (r&3)) << 4) + kperm16(j & 15).
// vth layout (paired, validated R12): per 256-half row r, element j at
//   pairoff(j, r) (+ j&1) — one LDS.128 per kb-pair per thread.
__device__ __half g_qh[NB*HW], g_ql[NB*HW];    // q hi/lo fp16 (3-term split)
__device__ __half g_kh[NB*HW], g_kl[NB*HW];    // k hi/lo fp16
__device__ __half g_vth[(size_t)NB*NC*HW];     // fp16 v^T [b][c][w][j], paired layout

// ---------------------------------------------------------------------------
// helpers
// ---------------------------------------------------------------------------
__device__ __forceinline__ uint32_t smem_u32(const void* p) {
    uint32_t a;
    asm("{ .reg .u64 t; cvta.to.shared.u64 t, %1; cvt.u32.u64 %0, t; }" : "=r"(a) : "l"(p));
    return a;
}
__device__ __forceinline__ uint2 lds64(uint32_t a) {
    uint2 v;
    asm volatile("ld.shared.v2.u32 {%0,%1}, [%2];" : "=r"(v.x), "=r"(v.y) : "r"(a));
    return v;
}
__device__ __forceinline__ uint4 lds128u(uint32_t a) {
    uint4 v;
    asm volatile("ld.shared.v4.u32 {%0,%1,%2,%3}, [%4];"
                 : "=r"(v.x), "=r"(v.y), "=r"(v.z), "=r"(v.w) : "r"(a));
    return v;
}
// exp(x) for x <= 0, FMA-pipe only: 2^(x*log2e), deg-6 poly
__device__ __forceinline__ float fast_exp(float x) {
    float t = fmaxf(x * 1.4426950408889634f, -126.0f);
    float n = rintf(t);
    float f = t - n;
    float p = fmaf(f, 0.00015403530393381609f, 0.0013333558146428443f);
    p = fmaf(f, p, 0.009618129107628477f);
    p = fmaf(f, p, 0.0555041086648216f);
    p = fmaf(f, p, 0.2402265069591007f);
    p = fmaf(f, p, 0.6931471805599453f);
    p = fmaf(f, p, 1.0f);
    return __int_as_float(__float_as_int(p) + (((int)n) << 23));
}
#define MBAR_INIT(a, n) asm volatile("mbarrier.init.shared.b64 [%0], %1;" :: "r"(a), "r"(n) : "memory")
#define MBAR_EXPECT(a, tx) asm volatile("mbarrier.arrive.expect_tx.shared.b64 _, [%0], %1;" :: "r"(a), "r"(tx) : "memory")
#define MBAR_WAIT(a, ph) do {                                                        \
    uint32_t _m = (a), _p = (ph), _d;                                                \
    asm volatile("{ .reg .pred p; mbarrier.try_wait.parity.acquire.cta.shared::cta.b64 p, [%1], %2; selp.b32 %0,1,0,p; }" \
                 : "=r"(_d) : "r"(_m), "r"(_p) : "memory");                          \
    if (!_d) {                                                                       \
      asm volatile("{ .reg .pred P1; WL%=: mbarrier.try_wait.parity.acquire.cta.shared::cta.b64 P1, [%0], %1, 0x989680; @P1 bra.uni WD%=; bra.uni WL%=; WD%=: }" \
                   :: "r"(_m), "r"(_p) : "memory");                                  \
    } } while (0)
#define BULK_G2S(sdst, gsrc, bytes, mbar)                                            \
    asm volatile("cp.async.bulk.shared::cta.global.mbarrier::complete_tx::bytes "    \
                 "[%0], [%1], %2, [%3];"                                             \
                 :: "r"(sdst), "l"(gsrc), "r"(bytes), "r"(mbar) : "memory")
#define MMA_F16(d, a0, a1, a2, a3, b0, b1)                                        \
    asm volatile("mma.sync.aligned.m16n8k16.row.col.f32.f16.f16.f32 "             \
                 "{%0,%1,%2,%3},{%4,%5,%6,%7},{%8,%9},{%0,%1,%2,%3};"             \
                 : "+f"(d[0]), "+f"(d[1]), "+f"(d[2]), "+f"(d[3])                  \
                 : "r"(a0), "r"(a1), "r"(a2), "r"(a3), "r"(b0), "r"(b1))

__device__ __forceinline__ int kperm16(int kb) {   // kb = k & 15
    int pk = kb >> 1;
    return ((((pk & 3) << 1) | (pk >> 2)) << 1) | (kb & 1);
}
// paired layout offset (halfs) for even j, row r:
__device__ __forceinline__ int pairoff(int j, int r) {
    int pk = (j & 15) >> 1;
    return (((j >> 5) ^ (r & 7)) << 5) + (pk & 3) * 8 + ((j >> 4) & 1) * 4
           + (pk >> 2) * 2;
}

// ---------------------------------------------------------------------------
// Kernel A: fused projections (validated R12). q,k -> fp16 hi/lo;
// v = w3@x + b3 transposed [b][c][w][j], fp16, paired layout.
// ---------------------------------------------------------------------------
__global__ __launch_bounds__(256)
void proj_kernel(const float* __restrict__ x,
                 const float* __restrict__ w1, const float* __restrict__ b1,
                 const float* __restrict__ w2, const float* __restrict__ b2,
                 const float* __restrict__ w3, const float* __restrict__ b3) {
    __shared__ float xt_s[8][32][33];
    __shared__ float w1s[8], w2s[8], w3s[64], b3s[8], bqk[2];
    const int tid = threadIdx.x;
    if (tid < 8)  { w1s[tid] = w1[tid]; w2s[tid] = w2[tid]; b3s[tid] = b3[tid]; }
    if (tid < 64) w3s[tid] = w3[tid];
    if (tid == 0) { bqk[0] = b1[0]; bqk[1] = b2[0]; }
    __syncthreads();
    const int b = blockIdx.z, j0 = blockIdx.y * 32, w0 = blockIdx.x * 32;
    const int jl = tid >> 3, wq = (tid & 7) << 2;
    const float* xb = x + (size_t)b * NC * HW + (size_t)(j0 + jl) * NW + w0 + wq;

    float4 xv[8];
#pragma unroll
    for (int c = 0; c < 8; c++) xv[c] = *(const float4*)(xb + (size_t)c * HW);

    float4 q = make_float4(bqk[0], bqk[0], bqk[0], bqk[0]);
    float4 k = make_float4(bqk[1], bqk[1], bqk[1], bqk[1]);
#pragma unroll
    for (int c = 0; c < 8; c++) {
        q.x = fmaf(w1s[c], xv[c].x, q.x); q.y = fmaf(w1s[c], xv[c].y, q.y);
        q.z = fmaf(w1s[c], xv[c].z, q.z); q.w = fmaf(w1s[c], xv[c].w, q.w);
        k.x = fmaf(w2s[c], xv[c].x, k.x); k.y = fmaf(w2s[c], xv[c].y, k.y);
        k.z = fmaf(w2s[c], xv[c].z, k.z); k.w = fmaf(w2s[c], xv[c].w, k.w);
    }
    {
        const int row = j0 + jl;
        const size_t rowoff = (size_t)b * HW + (size_t)row * NW;
        const int base = (((w0 + wq) >> 4) ^ (row & 3)) << 4;
        const int kb = wq & 15;
        const int h0 = base + kperm16(kb), h1 = base + kperm16(kb + 2);
        __half qhx = __float2half_rn(q.x), qhy = __float2half_rn(q.y);
        __half qhz = __float2half_rn(q.z), qhw = __float2half_rn(q.w);
        __half khx = __float2half_rn(k.x), khy = __float2half_rn(k.y);
        __half khz = __float2half_rn(k.z), khw = __float2half_rn(k.w);
        *(__half2*)(g_qh + rowoff + h0) = __halves2half2(qhx, qhy);
        *(__half2*)(g_qh + rowoff + h1) = __halves2half2(qhz, qhw);
        *(__half2*)(g_kh + rowoff + h0) = __halves2half2(khx, khy);
        *(__half2*)(g_kh + rowoff + h1) = __halves2half2(khz, khw);
        *(__half2*)(g_ql + rowoff + h0) = __floats2half2_rn(q.x - __half2float(qhx),
                                                            q.y - __half2float(qhy));
        *(__half2*)(g_ql + rowoff + h1) = __floats2half2_rn(q.z - __half2float(qhz),
                                                            q.w - __half2float(qhw));
        *(__half2*)(g_kl + rowoff + h0) = __floats2half2_rn(k.x - __half2float(khx),
                                                            k.y - __half2float(khy));
        *(__half2*)(g_kl + rowoff + h1) = __floats2half2_rn(k.z - __half2float(khz),
                                                            k.w - __half2float(khw));
    }

#pragma unroll
    for (int c = 0; c < 8; c++) {
        float4 v = make_float4(b3s[c], b3s[c], b3s[c], b3s[c]);
#pragma unroll
        for (int cp = 0; cp < 8; cp++) {
            float w = w3s[c * 8 + cp];
            v.x = fmaf(w, xv[cp].x, v.x); v.y = fmaf(w, xv[cp].y, v.y);
            v.z = fmaf(w, xv[cp].z, v.z); v.w = fmaf(w, xv[cp].w, v.w);
        }
        xt_s[c][jl][wq + 0] = v.x; xt_s[c][jl][wq + 1] = v.y;
        xt_s[c][jl][wq + 2] = v.z; xt_s[c][jl][wq + 3] = v.w;
    }
    __syncthreads();
    const int jp = (tid & 15) << 1, wl = tid >> 4;
#pragma unroll
    for (int c = 0; c < 8; c++)
#pragma unroll
        for (int ws = 0; ws < 32; ws += 16) {
            int wg = ws + wl;
            int idx = pairoff(j0 + jp, wg);
            *(__half2*)(g_vth + (((size_t)(b * 8 + c)) * NW + w0 + wg) * NH + idx) =
                __floats2half2_rn(xt_s[c][jp][wg], xt_s[c][jp + 1][wg]);
        }
}

// ---------------------------------------------------------------------------
// Kernel B: MERGED attention. Phase 1 = scores+softmax (validated);
// Phase 2 = out = attn @ vth, V streamed through a 2-SLOT 64KB HALF-CHANNEL
// RING in the dead q regions (the R12 serialization fix).
// CTA = (mt, b), 512 thr = 16 warps (4m x 4n).
// ---------------------------------------------------------------------------
#define SF_MB_F0 0
#define SF_MB_F1 8
#define SF_MB_A  16
#define SF_MB_V0 24
#define SF_MB_V1 32
#define SF_QH 1024
#define SF_QL (SF_QH + 65536)
#define SF_ATTN (SF_QL + 65536)       // k-ring during phase1, attn in phase2
#define SF_RED (SF_ATTN + 65536)
#define SMEM_FUSED (SF_RED + 2048)    // 199680

__global__ __launch_bounds__(512, 1)
void attention_kernel(float* __restrict__ out) {
    extern __shared__ char smem[];
    const uint32_t sb = smem_u32(smem);
    float* red = (float*)(smem + SF_RED);
    const int tid = threadIdx.x;
    const int lane = tid & 31, warp = tid >> 5;
    const int warpM = warp & 3, warpN = warp >> 2;
    const int g = lane >> 2, t4 = lane & 3;
    const uint32_t gx = (uint32_t)(g & 3);

    const int mt = blockIdx.x;
    const int b  = blockIdx.y;
    const int i0 = mt * 128;
    const __half* Aqh = g_qh + (size_t)b * HW + (size_t)i0 * NW;
    const __half* Aql = g_ql + (size_t)b * HW + (size_t)i0 * NW;
    const __half* Bkh = g_kh + (size_t)b * HW;
    const __half* Bkl = g_kl + (size_t)b * HW;
    const __half* Vb  = g_vth + ((size_t)(b * 8)) * HW;

    if (tid == 0) {
        MBAR_INIT(sb + SF_MB_F0, 1);
        MBAR_INIT(sb + SF_MB_F1, 1);
        MBAR_INIT(sb + SF_MB_A, 1);
        MBAR_INIT(sb + SF_MB_V0, 1);
        MBAR_INIT(sb + SF_MB_V1, 1);
    }
    __syncthreads();
    if (tid == 0) {
        MBAR_EXPECT(sb + SF_MB_A, 131072u);
        BULK_G2S(sb + SF_QH, Aqh, 65536u, sb + SF_MB_A);
        BULK_G2S(sb + SF_QL, Aql, 65536u, sb + SF_MB_A);
        MBAR_EXPECT(sb + SF_MB_F0, 32768u);
        BULK_G2S(sb + SF_ATTN,          Bkh, 16384u, sb + SF_MB_F0);
        BULK_G2S(sb + SF_ATTN + 16384,  Bkl, 16384u, sb + SF_MB_F0);
        MBAR_EXPECT(sb + SF_MB_F1, 32768u);
        BULK_G2S(sb + SF_ATTN + 32768,  Bkh + 32 * NH, 16384u, sb + SF_MB_F1);
        BULK_G2S(sb + SF_ATTN + 49152,  Bkl + 32 * NH, 16384u, sb + SF_MB_F1);
    }

    float acc[8][2][4];
#pragma unroll
    for (int t = 0; t < 8; t++)
#pragma unroll
        for (int mi = 0; mi < 2; mi++)
#pragma unroll
            for (int r = 0; r < 4; r++) acc[t][mi][r] = 0.f;

    MBAR_WAIT(sb + SF_MB_A, 0);

    const int nrow = warpN * 8 + g;
#pragma unroll
    for (int t = 0; t < 8; t++) {
        MBAR_WAIT(sb + ((t & 1) ? SF_MB_F1 : SF_MB_F0), (t >> 1) & 1);
        const uint32_t kh = sb + SF_ATTN + (t & 1) * 32768;
        const uint32_t kl = kh + 16384;
        for (int kb = 0; kb < 16; kb++) {
            const uint32_t off = ((uint32_t)(kb ^ (int)gx) << 5) + (uint32_t)(t4 * 8);
            uint32_t ah[2][4], al[2][4];
#pragma unroll
            for (int mi = 0; mi < 2; mi++) {
                int r0 = warpM * 32 + mi * 16 + g;
                uint2 h0 = lds64(sb + SF_QH + r0 * 512 + off);
                uint2 h1 = lds64(sb + SF_QH + (r0 + 8) * 512 + off);
                uint2 l0 = lds64(sb + SF_QL + r0 * 512 + off);
                uint2 l1 = lds64(sb + SF_QL + (r0 + 8) * 512 + off);
                ah[mi][0] = h0.x; ah[mi][1] = h1.x; ah[mi][2] = h0.y; ah[mi][3] = h1.y;
                al[mi][0] = l0.x; al[mi][1] = l1.x; al[mi][2] = l0.y; al[mi][3] = l1.y;
            }
            uint2 bh = lds64(kh + nrow * 512 + off);
            uint2 bl = lds64(kl + nrow * 512 + off);
#pragma unroll
            for (int mi = 0; mi < 2; mi++) {
                MMA_F16(acc[t][mi], ah[mi][0], ah[mi][1], ah[mi][2], ah[mi][3],
                        bh.x, bh.y);
                MMA_F16(acc[t][mi], ah[mi][0], ah[mi][1], ah[mi][2], ah[mi][3],
                        bl.x, bl.y);
                MMA_F16(acc[t][mi], al[mi][0], al[mi][1], al[mi][2], al[mi][3],
                        bh.x, bh.y);
            }
        }
        __syncthreads();
        if (tid == 0 && t < 6) {
            uint32_t mb = sb + ((t & 1) ? SF_MB_F1 : SF_MB_F0);
            MBAR_EXPECT(mb, 32768u);
            uint32_t dst = sb + SF_ATTN + (t & 1) * 32768;
            BULK_G2S(dst,         Bkh + (size_t)(t + 2) * 32 * NH, 16384u, mb);
            BULK_G2S(dst + 16384, Bkl + (size_t)(t + 2) * 32 * NH, 16384u, mb);
        }
    }
    // q regions now dead -> prime the 2-slot V ring (c=0 halves 0,1);
    // fills overlap the whole softmax + attn smem-store below.
    if (tid == 0) {
        MBAR_EXPECT(sb + SF_MB_V0, 65536u);
        BULK_G2S(sb + SF_QH, Vb, 65536u, sb + SF_MB_V0);
        MBAR_EXPECT(sb + SF_MB_V1, 65536u);
        BULK_G2S(sb + SF_QL, Vb + (size_t)128 * NH, 65536u, sb + SF_MB_V1);
    }

    // ---- softmax (in regs, cross-warp reduce via red[]) ----
    float rowv[4];
#pragma unroll
    for (int mi = 0; mi < 2; mi++)
#pragma unroll
        for (int h = 0; h < 2; h++) {
            float m = -FLT_MAX;
#pragma unroll
            for (int t = 0; t < 8; t++)
                m = fmaxf(m, fmaxf(acc[t][mi][h * 2], acc[t][mi][h * 2 + 1]));
            m = fmaxf(m, __shfl_xor_sync(0xffffffffu, m, 1));
            m = fmaxf(m, __shfl_xor_sync(0xffffffffu, m, 2));
            rowv[mi * 2 + h] = m;
        }
    if (t4 == 0) {
#pragma unroll
        for (int mi = 0; mi < 2; mi++)
#pragma unroll
            for (int h = 0; h < 2; h++)
                red[warpN * 128 + warpM * 32 + mi * 16 + h * 8 + g] = rowv[mi * 2 + h];
    }
    __syncthreads();
    float rowmax[4];
#pragma unroll
    for (int mi = 0; mi < 2; mi++)
#pragma unroll
        for (int h = 0; h < 2; h++) {
            int rl = warpM * 32 + mi * 16 + h * 8 + g;
            rowmax[mi * 2 + h] = fmaxf(fmaxf(red[rl], red[128 + rl]),
                                       fmaxf(red[256 + rl], red[384 + rl]));
        }
    __syncthreads();
#pragma unroll
    for (int mi = 0; mi < 2; mi++)
#pragma unroll
        for (int h = 0; h < 2; h++) {
            float m = rowmax[mi * 2 + h], s = 0.f;
#pragma unroll
            for (int t = 0; t < 8; t++) {
                float e0 = fast_exp(acc[t][mi][h * 2] - m);
                float e1 = fast_exp(acc[t][mi][h * 2 + 1] - m);
                acc[t][mi][h * 2] = e0; acc[t][mi][h * 2 + 1] = e1;
                s += e0 + e1;
            }
            s += __shfl_xor_sync(0xffffffffu, s, 1);
            s += __shfl_xor_sync(0xffffffffu, s, 2);
            rowv[mi * 2 + h] = s;
        }
    if (t4 == 0) {
#pragma unroll
        for (int mi = 0; mi < 2; mi++)
#pragma unroll
            for (int h = 0; h < 2; h++)
                red[warpN * 128 + warpM * 32 + mi * 16 + h * 8 + g] = rowv[mi * 2 + h];
    }
    __syncthreads();   // also: all k-ring reads done; SF_ATTN region reusable
    // ---- store attn (fp16) to smem in paired layout ----
#pragma unroll
    for (int mi = 0; mi < 2; mi++)
#pragma unroll
        for (int h = 0; h < 2; h++) {
            int rl = warpM * 32 + mi * 16 + h * 8 + g;
            float inv = 1.0f / (red[rl] + red[128 + rl] + red[256 + rl] + red[384 + rl]);
#pragma unroll
            for (int t = 0; t < 8; t++) {
                int j = t * 32 + warpN * 8 + t4 * 2;
                uint32_t addr = sb + SF_ATTN + rl * 512 + pairoff(j, rl) * 2;
                __half2 hv = __floats2half2_rn(acc[t][mi][h * 2] * inv,
                                               acc[t][mi][h * 2 + 1] * inv);
                asm volatile("st.shared.b32 [%0], %1;" :: "r"(addr),
                             "r"(*(uint32_t*)&hv) : "memory");
            }
        }
    __syncthreads();

    // ========== Phase 2: out[c] = attn @ vth[b][c], 16 half-channels ==========
    for (int hc = 0; hc < 16; hc++) {
        const int c = hc >> 1, nh = (hc & 1) * 128;
        const uint32_t vslot = sb + ((hc & 1) ? SF_QL : SF_QH);
        MBAR_WAIT(sb + ((hc & 1) ? SF_MB_V1 : SF_MB_V0), (hc >> 1) & 1);

        float oacc[2][4][4];
#pragma unroll
        for (int mi = 0; mi < 2; mi++)
#pragma unroll
            for (int ni = 0; ni < 4; ni++)
#pragma unroll
                for (int r = 0; r < 4; r++) oacc[mi][ni][r] = 0.f;

        for (int p = 0; p < 8; p++) {           // kb-pairs
            uint4 av[2][2];
#pragma unroll
            for (int mi = 0; mi < 2; mi++) {
                int r0 = warpM * 32 + mi * 16 + g;
                uint32_t xo = ((uint32_t)(p ^ (r0 & 7)) << 6) + (uint32_t)(t4 * 16);
                av[mi][0] = lds128u(sb + SF_ATTN + r0 * 512 + xo);
                av[mi][1] = lds128u(sb + SF_ATTN + (r0 + 8) * 512 + xo);
            }
#pragma unroll
            for (int ni = 0; ni < 4; ni++) {
                int n = warpN * 32 + ni * 8 + g;         // local row in 128-row slot
                uint32_t xo = ((uint32_t)(p ^ (n & 7)) << 6) + (uint32_t)(t4 * 16);
                uint4 bv = lds128u(vslot + n * 512 + xo);
#pragma unroll
                for (int mi = 0; mi < 2; mi++) {
                    MMA_F16(oacc[mi][ni], av[mi][0].x, av[mi][1].x,
                            av[mi][0].y, av[mi][1].y, bv.x, bv.y);
                    MMA_F16(oacc[mi][ni], av[mi][0].z, av[mi][1].z,
                            av[mi][0].w, av[mi][1].w, bv.z, bv.w);
                }
            }
        }

        __syncthreads();                        // all reads of this slot done
        if (tid == 0 && hc < 14) {
            const int hc2 = hc + 2;
            uint32_t mb = sb + ((hc2 & 1) ? SF_MB_V1 : SF_MB_V0);
            MBAR_EXPECT(mb, 65536u);
            BULK_G2S(vslot, Vb + ((size_t)(hc2 >> 1)) * HW
                              + (size_t)((hc2 & 1) * 128) * NH, 65536u, mb);
        }

        // epilogue (overlaps next fill)
        float* ob = out + ((size_t)(b * 8 + c)) * HW;
#pragma unroll
        for (int mi = 0; mi < 2; mi++) {
            int row = i0 + warpM * 32 + mi * 16 + g;
#pragma unroll
            for (int ni = 0; ni < 4; ni++) {
                int col = nh + warpN * 32 + ni * 8 + t4 * 2;
                *(float2*)(ob + (size_t)row * NW + col) =
                    make_float2(oacc[mi][ni][0], oacc[mi][ni][1]);
                *(float2*)(ob + (size_t)(row + 8) * NW + col) =
                    make_float2(oacc[mi][ni][2], oacc[mi][ni][3]);
            }
        }
    }
}

// ---------------------------------------------------------------------------
extern "C" void kernel_launch(void* const* d_in, const int* in_sizes, int n_in,
                              void* d_out, int out_size) {
    const float* x  = (const float*)d_in[0];
    const float* w1 = (const float*)d_in[1];
    const float* b1 = (const float*)d_in[2];
    const float* w2 = (const float*)d_in[3];
    const float* b2 = (const float*)d_in[4];
    const float* w3 = (const float*)d_in[5];
    const float* b3 = (const float*)d_in[6];
    float* out = (float*)d_out;

    static bool configured = false;
    if (!configured) {
        cudaFuncSetAttribute(attention_kernel,
                             cudaFuncAttributeMaxDynamicSharedMemorySize, SMEM_FUSED);
        configured = true;
    }

    dim3 ga(8, 8, NB);
    proj_kernel<<<ga, 256>>>(x, w1, b1, w2, b2, w3, b3);
    dim3 gs(2, NB);
    attention_kernel<<<gs, 512, SMEM_FUSED>>>(out);
}